// round 12
// baseline (speedup 1.0000x reference)
#include <cuda_runtime.h>

// Shift_14422500180434: 3x3 spatial shift "im2col-lite".
//   x:   [N=32, C=64, H=56, W=56] f32
//   out: [N=32, C*9=576, H=56, W=56] f32
//   out[n, c*9 + 3*dy + dx, h, w] = x[n, c, h+dy-1, w+dx-1]  (zero pad)
//
// FINAL (R8 config, best measured: 38.98us; resubmitted after repeated
// broker infra flakes — code is byte-identical to the passing R8 run).
// The kernel is at the DRAM write-bandwidth wall: 231MB stores + 25.7MB reads
// at ~6.6TB/s sustained (~82% of spec). Characterized and rejected: smem
// staging, h-pairing, STG.256, block 256/1024, plain stores.
//  - __stcs streaming stores: output is write-once, keep it out of L2's way.
//  - per-dy row streaming: 6 live row floats -> 25 regs.
//  - block=512: 8KB contiguous store burst per plane per block (best point).
//  - exact grid (3136*512 == total threads): no bounds guard.

#define N_ 32
#define C_ 64
#define H_ 56
#define W_ 56
#define W4_ 14              // W/4
#define PLANE_ (H_ * W_)    // 3136
#define TOTAL_THREADS_ (N_ * C_ * H_ * W4_)   // 1,605,632 = 3136 * 512

__global__ __launch_bounds__(512) void shift_kernel(
    const float* __restrict__ x, float* __restrict__ out)
{
    int t = blockIdx.x * blockDim.x + threadIdx.x;

    int w4 = t % W4_;
    int h  = (t / W4_) % H_;
    int c  = (t / (W4_ * H_)) % C_;
    int n  = t / (W4_ * H_ * C_);
    int w0 = w4 * 4;

    const float* __restrict__ xp = x + ((n * C_ + c) * H_) * (long)W_ + w0;

    // Output base for shift s=0 at this (n, c, h, w0); planes are PLANE_ apart.
    float* __restrict__ op =
        out + (((long)(n * (C_ * 9) + c * 9)) * H_ + h) * W_ + w0;

#pragma unroll
    for (int dy = 0; dy < 3; ++dy) {
        int hh = h + dy - 1;
        bool hv = ((unsigned)hh < (unsigned)H_);

        // row[j]: input float at (hh, w0 + j - 1), j = 0..5 (zero outside)
        float4 v = make_float4(0.f, 0.f, 0.f, 0.f);
        float left = 0.f, right = 0.f;
        if (hv) {
            const float* rp = xp + hh * W_;
            v = *reinterpret_cast<const float4*>(rp);
            if (w4 > 0)       left  = rp[-1];
            if (w4 < W4_ - 1) right = rp[4];
        }
        float r0 = left, r1 = v.x, r2 = v.y, r3 = v.z, r4 = v.w, r5 = right;

        float* o = op + (long)(dy * 3) * PLANE_;
        __stcs(reinterpret_cast<float4*>(o),
               make_float4(r0, r1, r2, r3));
        __stcs(reinterpret_cast<float4*>(o + PLANE_),
               make_float4(r1, r2, r3, r4));
        __stcs(reinterpret_cast<float4*>(o + 2 * PLANE_),
               make_float4(r2, r3, r4, r5));
    }
}

extern "C" void kernel_launch(void* const* d_in, const int* in_sizes, int n_in,
                              void* d_out, int out_size)
{
    const float* x = (const float*)d_in[0];
    float* out = (float*)d_out;
    const int threads = 512;
    const int blocks = TOTAL_THREADS_ / threads;  // 3136, exact
    shift_kernel<<<blocks, threads>>>(x, out);
}

// round 13
// speedup vs baseline: 1.0090x; 1.0090x over previous
#include <cuda_runtime.h>

// Shift_14422500180434: 3x3 spatial shift "im2col-lite".
//   x:   [N=32, C=64, H=56, W=56] f32
//   out: [N=32, C*9=576, H=56, W=56] f32
//   out[n, c*9 + 3*dy + dx, h, w] = x[n, c, h+dy-1, w+dx-1]  (zero pad)
//
// CONVERGED FINAL (validated 3x: 38.98 / 39.36 us). At the DRAM
// write-bandwidth wall: 231MB stores + 25.7MB reads at ~6.6TB/s sustained
// (~82% of 8TB/s spec, write-dominated stream). Measured and rejected:
// smem staging (R4), h-pairing (R5), STG.256 (R6), block 256/1024 (R7/R9),
// plain stores (R1).
//  - __stcs streaming stores: output is write-once, keep it out of L2's way.
//  - per-dy row streaming: 6 live row floats -> 25 regs, occ ~78%.
//  - block=512: 8KB contiguous store burst per plane per block (optimum).
//  - exact grid (3136*512 == total threads): no bounds guard.

#define N_ 32
#define C_ 64
#define H_ 56
#define W_ 56
#define W4_ 14              // W/4
#define PLANE_ (H_ * W_)    // 3136
#define TOTAL_THREADS_ (N_ * C_ * H_ * W4_)   // 1,605,632 = 3136 * 512

__global__ __launch_bounds__(512) void shift_kernel(
    const float* __restrict__ x, float* __restrict__ out)
{
    int t = blockIdx.x * blockDim.x + threadIdx.x;

    int w4 = t % W4_;
    int h  = (t / W4_) % H_;
    int c  = (t / (W4_ * H_)) % C_;
    int n  = t / (W4_ * H_ * C_);
    int w0 = w4 * 4;

    const float* __restrict__ xp = x + ((n * C_ + c) * H_) * (long)W_ + w0;

    // Output base for shift s=0 at this (n, c, h, w0); planes are PLANE_ apart.
    float* __restrict__ op =
        out + (((long)(n * (C_ * 9) + c * 9)) * H_ + h) * W_ + w0;

#pragma unroll
    for (int dy = 0; dy < 3; ++dy) {
        int hh = h + dy - 1;
        bool hv = ((unsigned)hh < (unsigned)H_);

        // row[j]: input float at (hh, w0 + j - 1), j = 0..5 (zero outside)
        float4 v = make_float4(0.f, 0.f, 0.f, 0.f);
        float left = 0.f, right = 0.f;
        if (hv) {
            const float* rp = xp + hh * W_;
            v = *reinterpret_cast<const float4*>(rp);
            if (w4 > 0)       left  = rp[-1];
            if (w4 < W4_ - 1) right = rp[4];
        }
        float r0 = left, r1 = v.x, r2 = v.y, r3 = v.z, r4 = v.w, r5 = right;

        float* o = op + (long)(dy * 3) * PLANE_;
        __stcs(reinterpret_cast<float4*>(o),
               make_float4(r0, r1, r2, r3));
        __stcs(reinterpret_cast<float4*>(o + PLANE_),
               make_float4(r1, r2, r3, r4));
        __stcs(reinterpret_cast<float4*>(o + 2 * PLANE_),
               make_float4(r2, r3, r4, r5));
    }
}

extern "C" void kernel_launch(void* const* d_in, const int* in_sizes, int n_in,
                              void* d_out, int out_size)
{
    const float* x = (const float*)d_in[0];
    float* out = (float*)d_out;
    const int threads = 512;
    const int blocks = TOTAL_THREADS_ / threads;  // 3136, exact
    shift_kernel<<<blocks, threads>>>(x, out);
}

// round 14
// speedup vs baseline: 1.0099x; 1.0008x over previous
#include <cuda_runtime.h>

// Shift_14422500180434: 3x3 spatial shift "im2col-lite".
//   x:   [N=32, C=64, H=56, W=56] f32
//   out: [N=32, C*9=576, H=56, W=56] f32
//   out[n, c*9 + 3*dy + dx, h, w] = x[n, c, h+dy-1, w+dx-1]  (zero pad)
//
// CONVERGED FINAL (validated 4x: 38.98 / 39.36 / 39.01 us). At the DRAM
// write-bandwidth wall: 231MB stores + 25.7MB reads at ~6.6TB/s sustained
// (~82% of 8TB/s spec, write-dominated stream). Measured and rejected:
// smem staging (R4), h-pairing (R5), STG.256 (R6), block 256/1024 (R7/R9),
// plain stores (R1).
//  - __stcs streaming stores: output is write-once, keep it out of L2's way.
//  - per-dy row streaming: 6 live row floats -> 25 regs, occ ~78%.
//  - block=512: 8KB contiguous store burst per plane per block (optimum).
//  - exact grid (3136*512 == total threads): no bounds guard.

#define N_ 32
#define C_ 64
#define H_ 56
#define W_ 56
#define W4_ 14              // W/4
#define PLANE_ (H_ * W_)    // 3136
#define TOTAL_THREADS_ (N_ * C_ * H_ * W4_)   // 1,605,632 = 3136 * 512

__global__ __launch_bounds__(512) void shift_kernel(
    const float* __restrict__ x, float* __restrict__ out)
{
    int t = blockIdx.x * blockDim.x + threadIdx.x;

    int w4 = t % W4_;
    int h  = (t / W4_) % H_;
    int c  = (t / (W4_ * H_)) % C_;
    int n  = t / (W4_ * H_ * C_);
    int w0 = w4 * 4;

    const float* __restrict__ xp = x + ((n * C_ + c) * H_) * (long)W_ + w0;

    // Output base for shift s=0 at this (n, c, h, w0); planes are PLANE_ apart.
    float* __restrict__ op =
        out + (((long)(n * (C_ * 9) + c * 9)) * H_ + h) * W_ + w0;

#pragma unroll
    for (int dy = 0; dy < 3; ++dy) {
        int hh = h + dy - 1;
        bool hv = ((unsigned)hh < (unsigned)H_);

        // row[j]: input float at (hh, w0 + j - 1), j = 0..5 (zero outside)
        float4 v = make_float4(0.f, 0.f, 0.f, 0.f);
        float left = 0.f, right = 0.f;
        if (hv) {
            const float* rp = xp + hh * W_;
            v = *reinterpret_cast<const float4*>(rp);
            if (w4 > 0)       left  = rp[-1];
            if (w4 < W4_ - 1) right = rp[4];
        }
        float r0 = left, r1 = v.x, r2 = v.y, r3 = v.z, r4 = v.w, r5 = right;

        float* o = op + (long)(dy * 3) * PLANE_;
        __stcs(reinterpret_cast<float4*>(o),
               make_float4(r0, r1, r2, r3));
        __stcs(reinterpret_cast<float4*>(o + PLANE_),
               make_float4(r1, r2, r3, r4));
        __stcs(reinterpret_cast<float4*>(o + 2 * PLANE_),
               make_float4(r2, r3, r4, r5));
    }
}

extern "C" void kernel_launch(void* const* d_in, const int* in_sizes, int n_in,
                              void* d_out, int out_size)
{
    const float* x = (const float*)d_in[0];
    float* out = (float*)d_out;
    const int threads = 512;
    const int blocks = TOTAL_THREADS_ / threads;  // 3136, exact
    shift_kernel<<<blocks, threads>>>(x, out);
}